// round 17
// baseline (speedup 1.0000x reference)
#include <cuda_runtime.h>
#include <math.h>

#define B_   32
#define TT_  512
#define TM_  2048
#define D_   512
#define M_   80
#define NEGF (-1e9f)

#define HEXP_ELEMS (B_*TM_*D_)       /* 33554432 */
#define LOSS_OFF   HEXP_ELEMS
#define DUR_OFF    (HEXP_ELEMS + 1)

typedef unsigned long long ull;

// ------------------- device scratch (no allocation allowed) -------------------
__device__ float g_hw[B_*TT_*M_];         // [b*Tt+i][80] = h @ W
__device__ float g_hb[B_*TT_];            // h @ b_proj
__device__ float g_S[(size_t)B_*TM_*TT_]; // [b][j][i] masked scores (128 MB)
__device__ int   g_idx[B_*TM_];           // frame -> token index
__device__ float g_lsq[B_];
__device__ float g_lcnt[B_];

// ------------------- f32x2 helpers -------------------
__device__ __forceinline__ ull pk2(float x, float y) {
    ull r;
    asm("mov.b64 %0, {%1,%2};" : "=l"(r) : "f"(x), "f"(y));
    return r;
}
__device__ __forceinline__ float2 upk2(ull v) {
    float2 r;
    asm("mov.b64 {%0,%1}, %2;" : "=f"(r.x), "=f"(r.y) : "l"(v));
    return r;
}
#define FMA2(d, a, b, c) asm("fma.rn.f32x2 %0, %1, %2, %3;" : "=l"(d) : "l"(a), "l"(b), "l"(c))

// =================== K1: hw = h @ W  + fused hb = h . b_proj  (frozen R14) ===================
__global__ void __launch_bounds__(256) k1_hw(const float* __restrict__ h,
                                             const float* __restrict__ w,
                                             const float* __restrict__ bp) {
    __shared__ float hS[64*68];   // [r][d] stride 68
    __shared__ float wS[64*84];   // [d][m] stride 84
    int tid  = threadIdx.x;
    int row0 = blockIdx.x * 64;
    int tx = tid & 15;
    int ty = tid >> 4;
    float acc[4][5];
#pragma unroll
    for (int r = 0; r < 4; r++)
#pragma unroll
        for (int m = 0; m < 5; m++) acc[r][m] = 0.f;

    float bacc[4] = {0.f, 0.f, 0.f, 0.f};
    const float4* bp4 = (const float4*)bp;

    for (int dc = 0; dc < D_; dc += 64) {
#pragma unroll
        for (int k = 0; k < 4; k++) {
            int l = tid + k*256;
            int r = l >> 4, d4 = l & 15;
            float4 v = *(const float4*)&h[(size_t)(row0 + r)*D_ + dc + d4*4];
            *(float4*)&hS[r*68 + d4*4] = v;
            float4 bv = bp4[(dc >> 2) + d4];
            bacc[k] += v.x*bv.x + v.y*bv.y + v.z*bv.z + v.w*bv.w;
        }
#pragma unroll
        for (int k = 0; k < 5; k++) {
            int l = tid + k*256;
            int d = l / 20, m4 = l % 20;
            float4 v = *(const float4*)&w[(size_t)(dc + d)*M_ + m4*4];
            *(float4*)&wS[d*84 + m4*4] = v;
        }
        __syncthreads();
#pragma unroll 8
        for (int d = 0; d < 64; d++) {
            float a0 = hS[(ty*4+0)*68 + d];
            float a1 = hS[(ty*4+1)*68 + d];
            float a2 = hS[(ty*4+2)*68 + d];
            float a3 = hS[(ty*4+3)*68 + d];
#pragma unroll
            for (int m = 0; m < 5; m++) {
                float bv = wS[d*84 + tx*5 + m];
                acc[0][m] += a0*bv; acc[1][m] += a1*bv;
                acc[2][m] += a2*bv; acc[3][m] += a3*bv;
            }
        }
        __syncthreads();
    }
#pragma unroll
    for (int r = 0; r < 4; r++)
#pragma unroll
        for (int m = 0; m < 5; m++)
            g_hw[(size_t)(row0 + ty*4 + r)*M_ + tx*5 + m] = acc[r][m];

#pragma unroll
    for (int k = 0; k < 4; k++) {
        float s = bacc[k];
        s += __shfl_down_sync(0xffffffffu, s, 8);
        s += __shfl_down_sync(0xffffffffu, s, 4);
        s += __shfl_down_sync(0xffffffffu, s, 2);
        s += __shfl_down_sync(0xffffffffu, s, 1);
        if ((tid & 15) == 0) g_hb[row0 + (tid >> 4) + 16*k] = s;
    }
}

// =================== K2: S[b][j][i] = masked(hw . mel + hb)  (R16 + no dead-block fill) ===================
// Fully-masked i-blocks (i0 >= tl) are NOT written at all: k3 provably never reads
// rows i >= tl (information flows upward in i; backtrack starts at tl-1).
__global__ void __launch_bounds__(256) k2_attn(const float* __restrict__ mel,
                                               const int* __restrict__ tlv,
                                               const int* __restrict__ mlv) {
    extern __shared__ float sm2[];
    float* melS = sm2;            // [80][132]
    float* hwS  = sm2 + 80*132;   // [80][129]
    int b  = blockIdx.z;
    int ml = mlv[b];
    int j0 = blockIdx.y * 128;
    if (j0 >= ml) return;
    int i0  = blockIdx.x * 128;
    int tlb = tlv[b];
    if (i0 >= tlb) return;        // dead rows: never read downstream
    int tid = threadIdx.x;
    int tx  = tid & 15;
    int ty  = tid >> 4;

    const float* melB = mel + (size_t)b*M_*TM_;
#pragma unroll
    for (int k = 0; k < 10; k++) {
        int l = tid + k*256;
        int m = l >> 5, j4 = l & 31;
        float4 v = *(const float4*)&melB[(size_t)m*TM_ + j0 + j4*4];
        *(float4*)&melS[m*132 + j4*4] = v;
    }
    const float* hwB = g_hw + (size_t)b*TT_*M_;
#pragma unroll
    for (int k = 0; k < 40; k++) {
        int l = tid + k*256;
        int m = l % 80, ii = l / 80;
        hwS[m*129 + ii] = hwB[(size_t)(i0+ii)*M_ + m];
    }
    __syncthreads();

    ull acc[4][8];                // [j-pair k][i index ik]
#pragma unroll
    for (int k = 0; k < 4; k++)
#pragma unroll
        for (int p = 0; p < 8; p++) acc[k][p] = 0ull;

#pragma unroll 2
    for (int m = 0; m < M_; m++) {
        ull mp[4];
#pragma unroll
        for (int k = 0; k < 4; k++)   // adjacent pair (j0+2ty+32k, +1): one LDS.64
            mp[k] = *(const ull*)&melS[m*132 + 2*ty + 32*k];
        ull hd[8];
#pragma unroll
        for (int ik = 0; ik < 8; ik++) {
            float hv = hwS[m*129 + tx + 16*ik];
            hd[ik] = pk2(hv, hv);
        }
#pragma unroll
        for (int k = 0; k < 4; k++)
#pragma unroll
            for (int ik = 0; ik < 8; ik++)
                FMA2(acc[k][ik], hd[ik], mp[k], acc[k][ik]);
    }

    float hbv[8];
    bool  msk[8];
#pragma unroll
    for (int ik = 0; ik < 8; ik++) {
        int ig = i0 + tx + 16*ik;
        hbv[ik] = g_hb[b*TT_ + ig];
        msk[ik] = (ig < tlb);
    }
#pragma unroll
    for (int k = 0; k < 4; k++) {
        int jlo = j0 + 2*ty + 32*k;
        int jhi = jlo + 1;
        float* rlo = g_S + ((size_t)b*TM_ + jlo)*TT_ + i0;
        float* rhi = g_S + ((size_t)b*TM_ + jhi)*TT_ + i0;
        bool blo = (jlo < ml), bhi = (jhi < ml);
#pragma unroll
        for (int ik = 0; ik < 8; ik++) {
            float2 v = upk2(acc[k][ik]);
            if (blo) rlo[tx + 16*ik] = msk[ik] ? (v.x + hbv[ik]) : NEGF;
            if (bhi) rhi[tx + 16*ik] = msk[ik] ? (v.y + hbv[ik]) : NEGF;
        }
    }
}

// =================== K3: MAS DP + backtrack — R5 structure + dead-row skip ===================
// act  (thread): i < tl  -> load S; else c = 0 (value never influences active rows).
// wact (warp): 32*wid < tl -> do updates; fully-dead warps only hit the barrier.
// Info flows upward in i and backtrack never visits i >= tl, so outputs are
// bit-identical to R5's. Barrier protocol untouched.
__global__ void __launch_bounds__(512) k3_dp(const float* __restrict__ ldp,
                                             const int* __restrict__ tlv,
                                             const int* __restrict__ mlv,
                                             float* __restrict__ out) {
    extern __shared__ unsigned int dsm[];
    unsigned int* ch   = dsm;                         // [512][65]
    float*        bnd  = (float*)(dsm + 512*65);      // [2][16]
    unsigned int* dur  = (unsigned int*)(bnd + 32);   // [512]
    unsigned int* wsum = dur + 512;                   // [16]
    float*        red  = (float*)(wsum + 16);         // [16]

    int b    = blockIdx.x;
    int i    = threadIdx.x;
    int lane = i & 31, wid = i >> 5;
    int tl = tlv[b], ml = mlv[b];
    const float* Sb = g_S + (size_t)b*TM_*TT_;

    bool act  = (i < tl);                 // this row matters
    bool wact = ((wid << 5) < tl);        // warp has at least one live row

    float q = (i == 0) ? Sb[0] : NEGF;
    unsigned int cw = 0;
    int p = 0;
    float c[8], n[8];
#pragma unroll
    for (int k = 0; k < 8; k++) {
        int j = 1 + k;
        c[k] = (j < ml && act) ? Sb[(size_t)j*TT_ + i] : 0.f;
    }

    for (int j0 = 1; j0 < ml; j0 += 8) {
#pragma unroll
        for (int k = 0; k < 8; k++) {          // prefetch next group (live rows only)
            int j = j0 + 8 + k;
            n[k] = (j < ml && act) ? Sb[(size_t)j*TT_ + i] : 0.f;
        }
#pragma unroll
        for (int k = 0; k < 8; k++) {
            int j = j0 + k;
            if (j < ml) {                       // uniform across block
                if (wact && lane == 31) bnd[p*16 + wid] = q;
                __syncthreads();
                if (wact) {                     // warp-uniform: shfl mask stays legal
                    float up = __shfl_up_sync(0xffffffffu, q, 1);
                    if (lane == 0) up = (wid == 0) ? NEGF : bnd[p*16 + wid - 1];
                    unsigned int take = (up > q) ? 1u : 0u;
                    q = c[k] + fmaxf(q, up);
                    cw |= take << (j & 31);
                    if ((j & 31) == 31) { ch[i*65 + (j >> 5)] = cw; cw = 0; }
                }
                p ^= 1;
            }
        }
#pragma unroll
        for (int k = 0; k < 8; k++) c[k] = n[k];
    }
    if (wact && ((ml - 1) & 31) != 31) ch[i*65 + ((ml - 1) >> 5)] = cw;
    dur[i] = 0;
    __syncthreads();

    if (i == 0) {                               // serial CLZ run-scan backtrack
        int ii = tl - 1, j = ml - 1;
        while (j >= 0) {
            if (ii == 0) { dur[0] += (unsigned)(j + 1); break; }
            unsigned int w = ch[ii*65 + (j >> 5)];
            int bit = j & 31;
            if (bit != 31) w &= (2u << bit) - 1u;
            if (w == 0) { dur[ii] += (unsigned)(bit + 1); j -= bit + 1; }
            else {
                int hb = 31 - __clz(w);
                int jp = (j & ~31) + hb;
                dur[ii] += (unsigned)(j - jp + 1);
                ii -= 1;
                j = jp - 1;
            }
        }
    }
    __syncthreads();

    unsigned int d = dur[i];
    out[DUR_OFF + b*TT_ + i] = (float)d;

    // loss partial
    float part = 0.f;
    if (act) {
        float lg = logf(fmaxf((float)d, 1.0f));
        float df = ldp[b*TT_ + i] - lg;
        part = df * df;
    }
#pragma unroll
    for (int o = 16; o; o >>= 1) part += __shfl_down_sync(0xffffffffu, part, o);
    if (lane == 0) red[wid] = part;

    // inclusive scan of dur -> frame index scatter
    unsigned int v = d;
#pragma unroll
    for (int o = 1; o < 32; o <<= 1) {
        unsigned int t = __shfl_up_sync(0xffffffffu, v, o);
        if (lane >= o) v += t;
    }
    if (lane == 31) wsum[wid] = v;
    __syncthreads();
    if (i < 16) {
        unsigned int s = wsum[i];
#pragma unroll
        for (int o = 1; o < 16; o <<= 1) {
            unsigned int t = __shfl_up_sync(0x0000ffffu, s, o);
            if ((i & 15) >= o) s += t;
        }
        wsum[i] = s;
        float ls = red[i];
#pragma unroll
        for (int o = 8; o; o >>= 1) ls += __shfl_down_sync(0x0000ffffu, ls, o);
        if (i == 0) { g_lsq[b] = ls; g_lcnt[b] = (float)tl; }
    }
    __syncthreads();
    unsigned int base = (wid == 0) ? 0u : wsum[wid - 1];
    unsigned int cend = base + v;
    unsigned int cstart = cend - d;
    for (unsigned int j = cstart; j < cend; j++) g_idx[b*TM_ + j] = i;
}

// =================== K5: expansion — 4 frames/thread, chained dedup (frozen R16) ===================
__global__ void __launch_bounds__(256) k5_expand(const float* __restrict__ h,
                                                 const int* __restrict__ mlv,
                                                 float* __restrict__ out) {
    if (blockIdx.y == 0 && blockIdx.z == 0 && threadIdx.x < 32) {
        float s = g_lsq[threadIdx.x], cc = g_lcnt[threadIdx.x];
#pragma unroll
        for (int o = 16; o; o >>= 1) {
            s  += __shfl_down_sync(0xffffffffu, s, o);
            cc += __shfl_down_sync(0xffffffffu, cc, o);
        }
        if (threadIdx.x == 0) out[LOSS_OFF] = s / cc;
    }
    int b  = blockIdx.z;
    int g  = threadIdx.x >> 7;                 // frame-quad group within block
    int c4 = threadIdx.x & 127;                // float4 lane within row
    int j0 = blockIdx.y * 8 + g * 4;           // frames j0..j0+3
    int ml = mlv[b];

    int4 idx4 = *(const int4*)&g_idx[b*TM_ + j0];
    const float* hb = h + (size_t)b*TT_*D_;
    float4 z = make_float4(0.f, 0.f, 0.f, 0.f);
    float4 v0 = z, v1 = z, v2 = z, v3 = z;
    if (j0 < ml)
        v0 = *(const float4*)&hb[(size_t)idx4.x*D_ + c4*4];
    if (j0 + 1 < ml)
        v1 = (idx4.y == idx4.x) ? v0 : *(const float4*)&hb[(size_t)idx4.y*D_ + c4*4];
    if (j0 + 2 < ml)
        v2 = (idx4.z == idx4.y) ? v1 : *(const float4*)&hb[(size_t)idx4.z*D_ + c4*4];
    if (j0 + 3 < ml)
        v3 = (idx4.w == idx4.z) ? v2 : *(const float4*)&hb[(size_t)idx4.w*D_ + c4*4];

    float* ob = out + ((size_t)(b*TM_ + j0))*D_ + c4*4;
    *(float4*)(ob)          = v0;
    *(float4*)(ob + D_)     = v1;
    *(float4*)(ob + 2*D_)   = v2;
    *(float4*)(ob + 3*D_)   = v3;
}

// =================== host launcher ===================
extern "C" void kernel_launch(void* const* d_in, const int* in_sizes, int n_in,
                              void* d_out, int out_size) {
    const float* h_text = (const float*)d_in[0];   // [32,512,512]
    const float* mel    = (const float*)d_in[1];   // [32,80,2048]
    const int*   tl     = (const int*)  d_in[2];   // [32]
    const int*   mlv    = (const int*)  d_in[3];   // [32]
    const float* w_proj = (const float*)d_in[4];   // [512,80]
    const float* b_proj = (const float*)d_in[5];   // [512]
    const float* ldp    = (const float*)d_in[6];   // [32,512]
    float* out = (float*)d_out;

    const int K2_SMEM = (80*132 + 80*129) * 4;                        // 83520
    const int K3_SMEM = (512*65 + 512 + 16 + 16) * 4 + 32 * 4;        // 135456
    cudaFuncSetAttribute(k2_attn, cudaFuncAttributeMaxDynamicSharedMemorySize, K2_SMEM);
    cudaFuncSetAttribute(k3_dp,   cudaFuncAttributeMaxDynamicSharedMemorySize, K3_SMEM);

    k1_hw<<<256, 256>>>(h_text, w_proj, b_proj);                // launch 1
    k2_attn<<<dim3(4, 16, 32), 256, K2_SMEM>>>(mel, tl, mlv);   // launch 2
    k3_dp<<<32, 512, K3_SMEM>>>(ldp, tl, mlv, out);             // launch 3
    k5_expand<<<dim3(1, 256, 32), 256>>>(h_text, mlv, out);     // launch 4
}